// round 1
// baseline (speedup 1.0000x reference)
#include <cuda_runtime.h>
#include <math.h>

#define NB 4096
#define NC 128
#define KC 32
#define ED 128
#define MATSZ 16777216ULL   // 4096*4096

// ---------------- scratch (device globals: no allocation allowed) -------------
__device__ int   g_idx[NB];          // [c][k] -> building id
__device__ float d_netc[NB];         // net at (c,k)
__device__ float d_prioc[NB];        // priority at (c,k)
__device__ float d_hic[NB * ED];     // hi gathered per (c,k)
__device__ float d_hjc[NB * ED];     // hj gathered per (c,k)
__device__ float d_dist[NC * KC * KC];
__device__ float d_effc[NC * KC * KC];
__device__ float d_pflow[NC * KC * KC];
__device__ float d_partial[NC];

// ---------------- 1. fill output: sharing=0, effmat=1 ------------------------
__global__ void fill_kernel(float* __restrict__ out) {
    size_t idx = (size_t)blockIdx.x * blockDim.x + threadIdx.x; // float4 index
    float4 v = (idx < (MATSZ / 4)) ? make_float4(0.f, 0.f, 0.f, 0.f)
                                   : make_float4(1.f, 1.f, 1.f, 1.f);
    reinterpret_cast<float4*>(out)[idx] = v;
}

// ---------------- 2. stable grouping (counting-compaction per cluster) -------
__global__ void group_kernel(const int* __restrict__ assign,
                             const float* __restrict__ gen,
                             const float* __restrict__ cons,
                             const int* __restrict__ hour_p) {
    int warp = blockIdx.x * (blockDim.x >> 5) + (threadIdx.x >> 5);
    int lane = threadIdx.x & 31;
    int c = warp;                       // 0..127
    int count = 0;
    for (int base = 0; base < NB; base += 32) {
        int a = assign[base + lane];
        unsigned mask = __ballot_sync(0xffffffffu, a == c);
        if (a == c) {
            int pos = count + __popc(mask & ((1u << lane) - 1u));
            if (pos < KC) g_idx[c * KC + pos] = base + lane;
        }
        count += __popc(mask);
    }
    __syncwarp();
    int h = hour_p ? *hour_p : 12;
    if (lane < KC) {
        int b = g_idx[c * KC + lane];
        d_netc[c * KC + lane] = gen[b * 24 + h] - cons[b * 24 + h];
    }
}

// ---------------- 3. hi/hj GEMM: [32,128] x [128,256] per cluster -------------
__global__ void __launch_bounds__(256) hij_kernel(const float* __restrict__ emb,
                                                  const float* __restrict__ fpw1) {
    __shared__ float s_emb[KC][ED];     // 16KB
    int c = blockIdx.x;
    int tid = threadIdx.x;
    for (int i = tid; i < KC * ED; i += 256) {
        int r = i >> 7, e = i & 127;
        s_emb[r][e] = emb[(size_t)g_idx[c * KC + r] * ED + e];
    }
    __syncthreads();
    // thread t < 128: hi column t (W1a row t); t >= 128: hj column t-128 (W1b)
    const float* wrow = (tid < 128) ? (fpw1 + (size_t)tid * 258)
                                    : (fpw1 + (size_t)(tid - 128) * 258 + 128);
    float acc[KC];
#pragma unroll
    for (int r = 0; r < KC; r++) acc[r] = 0.f;
    for (int kc = 0; kc < ED; kc += 32) {
        float w[32];
#pragma unroll
        for (int q = 0; q < 32; q++) w[q] = __ldg(wrow + kc + q);
#pragma unroll
        for (int r = 0; r < KC; r++) {
#pragma unroll
            for (int q = 0; q < 32; q++)
                acc[r] = fmaf(s_emb[r][kc + q], w[q], acc[r]);
        }
    }
    float* dst = (tid < 128) ? d_hic : d_hjc;
    int col = tid & 127;
#pragma unroll 4
    for (int r = 0; r < KC; r++)
        dst[(size_t)(c * KC + r) * ED + col] = acc[r];
}

// ---------------- 4. priority MLP: 128->32->1, warp per building --------------
__global__ void prio_kernel(const float* __restrict__ emb,
                            const float* __restrict__ psw1,
                            const float* __restrict__ psb1,
                            const float* __restrict__ psw2,
                            const float* __restrict__ psb2) {
    int warp = blockIdx.x * (blockDim.x >> 5) + (threadIdx.x >> 5); // slot (c*32+k)
    int lane = threadIdx.x & 31;
    int b = g_idx[warp];
    const float* er = emb + (size_t)b * ED;
    const float* wr = psw1 + (size_t)lane * ED;
    float acc = psb1[lane];
#pragma unroll 8
    for (int e = 0; e < ED; e++) acc = fmaf(__ldg(er + e), __ldg(wr + e), acc);
    float h = fmaxf(acc, 0.f);
    float v = h * psw2[lane];
#pragma unroll
    for (int o = 16; o > 0; o >>= 1) v += __shfl_down_sync(0xffffffffu, v, o);
    if (lane == 0)
        d_prioc[warp] = 1.f / (1.f + expf(-(v + psb2[0])));
}

// ---------------- 5. pairwise dist + efficiency MLP ---------------------------
__global__ void dist_eff_kernel(const float* __restrict__ pos,
                                const float* __restrict__ enw1,
                                const float* __restrict__ enb1,
                                const float* __restrict__ enw2,
                                const float* __restrict__ enb2) {
    __shared__ float2 s_pos[KC];
    __shared__ float s_w1[16], s_b1[16], s_w2[16];
    int c = blockIdx.x, tid = threadIdx.x;
    if (tid < KC) {
        int b = g_idx[c * KC + tid];
        s_pos[tid] = make_float2(pos[b * 2], pos[b * 2 + 1]);
    }
    if (tid < 16) { s_w1[tid] = enw1[tid]; s_b1[tid] = enb1[tid]; s_w2[tid] = enw2[tid]; }
    __syncthreads();
    float b2v = enb2[0];
    for (int p = tid; p < KC * KC; p += blockDim.x) {
        int i = p >> 5, j = p & 31;
        float dx = s_pos[i].x - s_pos[j].x;
        float dy = s_pos[i].y - s_pos[j].y;
        float dist = sqrtf(dx * dx + dy * dy);
        float t = dist * (1.f / 1000.f);
        float s = 0.f;
#pragma unroll
        for (int l = 0; l < 16; l++)
            s = fmaf(fmaxf(fmaf(t, s_w1[l], s_b1[l]), 0.f), s_w2[l], s);
        float eff = 0.85f + 0.13f / (1.f + expf(-(s + b2v)));
        d_dist[c * KC * KC + p] = dist;
        d_effc[c * KC * KC + p] = eff;
    }
}

// ---------------- 6. flow MLP: the heavy kernel (warp per pair) ---------------
// h1[128] = relu(hi[i]+hj[j]+dist*w1d+hour*w1h+b1); h2=relu(h1@W2^T+b2);
// pflow = softplus(h2.w3 + b3)
__global__ void __launch_bounds__(256) pflow_kernel(const float* __restrict__ fpw1,
                                                    const float* __restrict__ fpb1,
                                                    const float* __restrict__ fpw2,
                                                    const float* __restrict__ fpb2,
                                                    const float* __restrict__ fpw3,
                                                    const float* __restrict__ fpb3,
                                                    const int* __restrict__ hour_p) {
    __shared__ float2 s_w2[ED][32];   // (w2[m][k], w2[m+32][k])  32KB
    __shared__ float s_w1d[ED];
    __shared__ float s_cvec[ED];      // hour_f*w1h + b1
    __shared__ float s_dist[KC * KC]; // 4KB
    __shared__ float s_h1[8][ED];     // per-warp staging, 4KB
    int c = blockIdx.x, tid = threadIdx.x;
    int w = tid >> 5, lane = tid & 31;
    float hour_f = (float)(hour_p ? *hour_p : 12) * (1.f / 24.f);
    for (int k = tid; k < ED; k += 256) {
        s_w1d[k] = fpw1[(size_t)k * 258 + 256];
        s_cvec[k] = fmaf(hour_f, fpw1[(size_t)k * 258 + 257], fpb1[k]);
    }
    for (int i = tid; i < ED * 32; i += 256) {
        int k = i >> 5, m = i & 31;
        s_w2[k][m] = make_float2(fpw2[(size_t)m * ED + k], fpw2[(size_t)(m + 32) * ED + k]);
    }
    for (int p = tid; p < KC * KC; p += 256) s_dist[p] = d_dist[c * KC * KC + p];
    __syncthreads();

    float b2a = fpb2[lane], b2b = fpb2[lane + 32];
    float w3a = fpw3[lane], w3b = fpw3[lane + 32];
    float b3 = fpb3[0];
    const float* hibase = d_hic + (size_t)c * KC * ED;
    const float* hjbase = d_hjc + (size_t)c * KC * ED;

    for (int p = w; p < KC * KC; p += 8) {
        int i = p >> 5, j = p & 31;
        float dd = s_dist[p];
        const float* hi = hibase + (size_t)i * ED;
        const float* hj = hjbase + (size_t)j * ED;
#pragma unroll
        for (int t = 0; t < 4; t++) {
            int k = lane + t * 32;
            float h1 = fmaf(dd, s_w1d[k], s_cvec[k]) + hi[k] + hj[k];
            s_h1[w][k] = fmaxf(h1, 0.f);
        }
        __syncwarp();
        float acca = b2a, accb = b2b;
#pragma unroll
        for (int k = 0; k < ED; k++) {
            float h1 = s_h1[w][k];
            float2 wv = s_w2[k][lane];
            acca = fmaf(h1, wv.x, acca);
            accb = fmaf(h1, wv.y, accb);
        }
        float v = fmaxf(acca, 0.f) * w3a + fmaxf(accb, 0.f) * w3b;
#pragma unroll
        for (int o = 16; o > 0; o >>= 1) v += __shfl_down_sync(0xffffffffu, v, o);
        if (lane == 0) {
            float x = v + b3;
            d_pflow[c * KC * KC + p] = (x > 20.f) ? x : log1pf(expf(x));
        }
        __syncwarp();
    }
}

// ---------------- 7. greedy allocation + scatter (block=warp per cluster) ----
__global__ void greedy_kernel(float* __restrict__ out) {
    __shared__ float s_effo[KC][KC];
    __shared__ float s_pfo[KC][KC];
    __shared__ float s_flow[KC][KC];
    __shared__ int   s_act[KC][KC];
    __shared__ float s_prio[KC];
    __shared__ float s_neto[KC];   // net sorted by priority
    __shared__ int   s_order[KC];
    __shared__ float s_dnet[KC];
    int c = blockIdx.x, lane = threadIdx.x;

    s_prio[lane] = d_prioc[c * KC + lane];
    float netme = d_netc[c * KC + lane];
    __syncwarp();
    // stable descending rank (ties -> lower original index first)
    float p = s_prio[lane];
    int r = 0;
#pragma unroll
    for (int l = 0; l < KC; l++) {
        float q = s_prio[l];
        r += (q > p) || (q == p && l < lane);
    }
    s_order[r] = lane;
    __syncwarp();
    int oi = s_order[lane];
    s_neto[lane] = d_netc[c * KC + oi];
    const float* effb = d_effc + c * KC * KC;
    const float* pfb  = d_pflow + c * KC * KC;
#pragma unroll 4
    for (int sj = 0; sj < KC; sj++) {
        int oj = s_order[sj];
        s_effo[lane][sj] = effb[oi * KC + oj];
        s_pfo[lane][sj]  = pfb[oi * KC + oj];
    }
    __syncwarp();

    if (lane == 0) {
        float dn[KC];
#pragma unroll
        for (int j = 0; j < KC; j++) dn[j] = s_neto[j];
        for (int i = 0; i < KC; i++) {
            float avail = fmaxf(s_neto[i], 0.f);
            if (avail > 0.f) {
#pragma unroll
                for (int j = 0; j < KC; j++) {
                    float needed = -dn[j];
                    bool active = (avail > 0.f) && (needed > 0.f);
                    float f = active ? fminf(fminf(avail, needed), s_pfo[i][j]) : 0.f;
                    dn[j] += f * s_effo[i][j];
                    avail -= f;
                    s_flow[i][j] = f;
                    s_act[i][j] = active ? 1 : 0;
                }
            } else {
#pragma unroll
                for (int j = 0; j < KC; j++) { s_flow[i][j] = 0.f; s_act[i][j] = 0; }
            }
        }
#pragma unroll
        for (int j = 0; j < KC; j++) s_dnet[j] = dn[j];
    }
    __syncwarp();

    // scatter (lane = sorted row index)
    float* out_sh = out;
    float* out_ef = out + MATSZ;
    float* out_sent = out + 2 * MATSZ + 1;
    float* out_recv = out_sent + NB;
    float* out_na   = out_recv + NB;

    int gi = g_idx[c * KC + oi];
    float sent = 0.f;
#pragma unroll 4
    for (int sj = 0; sj < KC; sj++) {
        float f = s_flow[lane][sj];
        sent += f;
        if (s_act[lane][sj]) {
            int gj = g_idx[c * KC + s_order[sj]];
            out_sh[(size_t)gi * NB + gj] = f;
            out_ef[(size_t)gi * NB + gj] = s_effo[lane][sj];
        }
    }
    out_sent[gi] = sent;
    float dnl = s_dnet[lane];
    out_recv[gi] = dnl - s_neto[lane];
    out_na[gi]   = dnl;

    float v = sent;
#pragma unroll
    for (int o = 16; o > 0; o >>= 1) v += __shfl_down_sync(0xffffffffu, v, o);
    if (lane == 0) d_partial[c] = v;
}

// ---------------- 8. deterministic total reduction ----------------------------
__global__ void total_kernel(float* __restrict__ out) {
    __shared__ float s[NC];
    int t = threadIdx.x;
    s[t] = d_partial[t];
    __syncthreads();
    for (int o = 64; o > 0; o >>= 1) {
        if (t < o) s[t] += s[t + o];
        __syncthreads();
    }
    if (t == 0) out[2 * MATSZ] = s[0];
}

// ------------------------------------------------------------------------------
extern "C" void kernel_launch(void* const* d_in, const int* in_sizes, int n_in,
                              void* d_out, int out_size) {
    const float* emb   = (const float*)d_in[0];
    const float* gen   = (const float*)d_in[1];
    const float* cons  = (const float*)d_in[2];
    const float* pos   = (const float*)d_in[3];
    const float* fpw1  = (const float*)d_in[4];
    const float* fpb1  = (const float*)d_in[5];
    const float* fpw2  = (const float*)d_in[6];
    const float* fpb2  = (const float*)d_in[7];
    const float* fpw3  = (const float*)d_in[8];
    const float* fpb3  = (const float*)d_in[9];
    const float* enw1  = (const float*)d_in[10];
    const float* enb1  = (const float*)d_in[11];
    const float* enw2  = (const float*)d_in[12];
    const float* enb2  = (const float*)d_in[13];
    const float* psw1  = (const float*)d_in[14];
    const float* psb1  = (const float*)d_in[15];
    const float* psw2  = (const float*)d_in[16];
    const float* psb2  = (const float*)d_in[17];
    const int*   assign = (const int*)d_in[18];
    const int*   hour   = (n_in >= 21) ? (const int*)d_in[20] : nullptr;
    float* out = (float*)d_out;

    fill_kernel<<<32768, 256>>>(out);
    group_kernel<<<16, 256>>>(assign, gen, cons, hour);
    hij_kernel<<<NC, 256>>>(emb, fpw1);
    prio_kernel<<<512, 256>>>(emb, psw1, psb1, psw2, psb2);
    dist_eff_kernel<<<NC, 256>>>(pos, enw1, enb1, enw2, enb2);
    pflow_kernel<<<NC, 256>>>(fpw1, fpb1, fpw2, fpb2, fpw3, fpb3, hour);
    greedy_kernel<<<NC, KC>>>(out);
    total_kernel<<<1, NC>>>(out);
}

// round 2
// speedup vs baseline: 1.3608x; 1.3608x over previous
#include <cuda_runtime.h>
#include <math.h>

#define NB 4096
#define NC 128
#define KC 32
#define ED 128
#define MATSZ 16777216ULL   // 4096*4096

// ---------------- scratch (device globals: no allocation allowed) -------------
__device__ int   g_idx[NB];          // [c][k] -> building id
__device__ float d_netc[NB];         // net at (c,k)
__device__ float d_prioc[NB];        // priority at (c,k)
__device__ float d_hic[NB * ED];     // hi gathered per (c,k)
__device__ float d_hjc[NB * ED];     // hj gathered per (c,k)
__device__ float d_dist[NC * KC * KC];
__device__ float d_effc[NC * KC * KC];
__device__ float d_pflow[NC * KC * KC];
__device__ float d_partial[NC];

// ---------------- packed f32x2 helpers ----------------------------------------
__device__ __forceinline__ unsigned long long fma2(unsigned long long a,
                                                   unsigned long long b,
                                                   unsigned long long c) {
    unsigned long long d;
    asm("fma.rn.f32x2 %0, %1, %2, %3;" : "=l"(d) : "l"(a), "l"(b), "l"(c));
    return d;
}
#define PK2(v, lo, hi)  asm("mov.b64 %0, {%1, %2};" : "=l"(v) : "f"(lo), "f"(hi))
#define UNPK2(lo, hi, v) asm("mov.b64 {%0, %1}, %2;" : "=f"(lo), "=f"(hi) : "l"(v))

// ---------------- 1. stable grouping (counting-compaction per cluster) -------
__global__ void group_kernel(const int* __restrict__ assign,
                             const float* __restrict__ gen,
                             const float* __restrict__ cons,
                             const int* __restrict__ hour_p) {
    int warp = blockIdx.x * (blockDim.x >> 5) + (threadIdx.x >> 5);
    int lane = threadIdx.x & 31;
    int c = warp;                       // 0..127
    int count = 0;
    for (int base = 0; base < NB; base += 32) {
        int a = assign[base + lane];
        unsigned mask = __ballot_sync(0xffffffffu, a == c);
        if (a == c) {
            int pos = count + __popc(mask & ((1u << lane) - 1u));
            if (pos < KC) g_idx[c * KC + pos] = base + lane;
        }
        count += __popc(mask);
    }
    __syncwarp();
    int h = hour_p ? *hour_p : 12;
    if (lane < KC) {
        int b = g_idx[c * KC + lane];
        d_netc[c * KC + lane] = gen[b * 24 + h] - cons[b * 24 + h];
    }
}

// ---------------- 2. hi/hj GEMM: [32,128] x [128,256] per cluster -------------
__global__ void __launch_bounds__(256) hij_kernel(const float* __restrict__ emb,
                                                  const float* __restrict__ fpw1) {
    __shared__ float s_emb[KC][ED];     // 16KB
    __shared__ float s_wt[32][256];     // 32KB  (k-chunk x out-col, transposed)
    int c = blockIdx.x;
    int t = threadIdx.x;
    for (int i = t; i < KC * ED; i += 256) {
        int r = i >> 7, e = i & 127;
        s_emb[r][e] = emb[(size_t)g_idx[c * KC + r] * ED + e];
    }
    float acc[KC];
#pragma unroll
    for (int r = 0; r < KC; r++) acc[r] = 0.f;

    for (int kc = 0; kc < 4; kc++) {
        __syncthreads();
        // stage transposed weight chunk: s_wt[kk][col] (coalesced over kk)
        for (int i = t; i < 32 * 256; i += 256) {
            int col = i >> 5, kk = i & 31;
            float v = (col < 128)
                ? fpw1[(size_t)col * 258 + kc * 32 + kk]
                : fpw1[(size_t)(col - 128) * 258 + 128 + kc * 32 + kk];
            s_wt[kk][col] = v;
        }
        __syncthreads();
        float w[32];
#pragma unroll
        for (int kk = 0; kk < 32; kk++) w[kk] = s_wt[kk][t];
#pragma unroll
        for (int r = 0; r < KC; r++) {
#pragma unroll
            for (int kk = 0; kk < 32; kk++)
                acc[r] = fmaf(s_emb[r][kc * 32 + kk], w[kk], acc[r]);
        }
    }
    float* dst = (t < 128) ? d_hic : d_hjc;
    int col = t & 127;
#pragma unroll 4
    for (int r = 0; r < KC; r++)
        dst[(size_t)(c * KC + r) * ED + col] = acc[r];
}

// ---------------- 3. priority MLP: 128->32->1 (shared-staged weights) ---------
__global__ void __launch_bounds__(256) prio_kernel(const float* __restrict__ emb,
                                                   const float* __restrict__ psw1,
                                                   const float* __restrict__ psb1,
                                                   const float* __restrict__ psw2,
                                                   const float* __restrict__ psb2) {
    __shared__ float s_w[32][129];     // padded: conflict-free column reads
    __shared__ float s_e[8][128];
    __shared__ float s_b1[32], s_w2s[32];
    int t = threadIdx.x, w = t >> 5, lane = t & 31;
    for (int i = t; i < 32 * 128; i += 256) {
        int m = i >> 7, e = i & 127;
        s_w[m][e] = psw1[i];
    }
    if (t < 32) { s_b1[t] = psb1[t]; s_w2s[t] = psw2[t]; }
    int slot = blockIdx.x * 8 + w;
    int b = g_idx[slot];
    ((float4*)s_e[w])[lane] = ((const float4*)(emb + (size_t)b * ED))[lane];
    __syncthreads();
    float acc = s_b1[lane];
#pragma unroll 16
    for (int e = 0; e < 128; e++)
        acc = fmaf(s_e[w][e], s_w[lane][e], acc);
    float v = fmaxf(acc, 0.f) * s_w2s[lane];
#pragma unroll
    for (int o = 16; o > 0; o >>= 1) v += __shfl_xor_sync(0xffffffffu, v, o);
    if (lane == 0)
        d_prioc[slot] = 1.f / (1.f + expf(-(v + psb2[0])));
}

// ---------------- 4. pairwise dist + efficiency MLP ---------------------------
__global__ void dist_eff_kernel(const float* __restrict__ pos,
                                const float* __restrict__ enw1,
                                const float* __restrict__ enb1,
                                const float* __restrict__ enw2,
                                const float* __restrict__ enb2) {
    __shared__ float2 s_pos[KC];
    __shared__ float s_w1[16], s_b1[16], s_w2[16];
    int c = blockIdx.x, tid = threadIdx.x;
    if (tid < KC) {
        int b = g_idx[c * KC + tid];
        s_pos[tid] = make_float2(pos[b * 2], pos[b * 2 + 1]);
    }
    if (tid < 16) { s_w1[tid] = enw1[tid]; s_b1[tid] = enb1[tid]; s_w2[tid] = enw2[tid]; }
    __syncthreads();
    float b2v = enb2[0];
    for (int p = tid; p < KC * KC; p += blockDim.x) {
        int i = p >> 5, j = p & 31;
        float dx = s_pos[i].x - s_pos[j].x;
        float dy = s_pos[i].y - s_pos[j].y;
        float dist = sqrtf(dx * dx + dy * dy);
        float t = dist * (1.f / 1000.f);
        float s = 0.f;
#pragma unroll
        for (int l = 0; l < 16; l++)
            s = fmaf(fmaxf(fmaf(t, s_w1[l], s_b1[l]), 0.f), s_w2[l], s);
        float eff = 0.85f + 0.13f / (1.f + expf(-(s + b2v)));
        d_dist[c * KC * KC + p] = dist;
        d_effc[c * KC * KC + p] = eff;
    }
}

// ---------------- 5. flow MLP: FFMA2 register-tiled GEMM + folded fill --------
// dynamic smem layout:
//   [0, 32768)        : s_h1  duplicated pairs  (32 j x 128 k) as float2(h,h)
//   [32768, 67584)    : s_w2  transposed [k][n], row padded to 68 floats
//   [67584, 71680)    : s_dist (1024 floats)
#define PF_SMEM 71680
__global__ void __launch_bounds__(256, 1) pflow_kernel(
        const float* __restrict__ fpw1, const float* __restrict__ fpb1,
        const float* __restrict__ fpw2, const float* __restrict__ fpb2,
        const float* __restrict__ fpw3, const float* __restrict__ fpb3,
        const int* __restrict__ hour_p, float* __restrict__ out) {
    extern __shared__ char sm[];
    unsigned long long* s_h1u = (unsigned long long*)sm;
    float2* s_h1f2 = (float2*)sm;
    float* s_w2 = (float*)(sm + 32768);
    const ulonglong2* s_w2u2 = (const ulonglong2*)(sm + 32768);
    float* s_dist = (float*)(sm + 67584);
    int c = blockIdx.x, t = threadIdx.x;

    // folded default-fill of the two big output matrices (overlaps with compute)
    {
        float4 v = (c < 64) ? make_float4(0.f, 0.f, 0.f, 0.f)
                            : make_float4(1.f, 1.f, 1.f, 1.f);
        float4* dst = ((float4*)out) + (size_t)c * 65536;
        for (int idx = t; idx < 65536; idx += 256) dst[idx] = v;
    }

    float hour_f = (float)(hour_p ? *hour_p : 12) * (1.f / 24.f);

    // stage W2 transposed: s_w2[k*68 + n] = fpw2[n*128 + k]  (coalesced over k)
    for (int i = t; i < 64 * 128; i += 256) {
        int k = i & 127, n = i >> 7;
        s_w2[k * 68 + n] = fpw2[n * 128 + k];
    }
    for (int i = t; i < 1024; i += 256) s_dist[i] = d_dist[c * 1024 + i];
    __syncthreads();

    // GEMM thread mapping: tx = n-quad (16), jp = j-pair (16)
    int tx = t & 15, jp = t >> 4;
    int j0 = jp * 2, j1 = j0 + 1;
    int n0 = tx * 4;
    // build mapping: kq = k-quad (32), jb = j base (8); j = chunk*8 + jb
    int kq = t & 31, k0 = kq * 4, jb = t >> 5;

    // per-thread constants
    float4 w1dq, cvq;
    w1dq.x = fpw1[(size_t)(k0 + 0) * 258 + 256];
    w1dq.y = fpw1[(size_t)(k0 + 1) * 258 + 256];
    w1dq.z = fpw1[(size_t)(k0 + 2) * 258 + 256];
    w1dq.w = fpw1[(size_t)(k0 + 3) * 258 + 256];
    cvq.x = fmaf(hour_f, fpw1[(size_t)(k0 + 0) * 258 + 257], fpb1[k0 + 0]);
    cvq.y = fmaf(hour_f, fpw1[(size_t)(k0 + 1) * 258 + 257], fpb1[k0 + 1]);
    cvq.z = fmaf(hour_f, fpw1[(size_t)(k0 + 2) * 258 + 257], fpb1[k0 + 2]);
    cvq.w = fmaf(hour_f, fpw1[(size_t)(k0 + 3) * 258 + 257], fpb1[k0 + 3]);

    const float* hjb = d_hjc + (size_t)c * KC * ED;
    const float* hib = d_hic + (size_t)c * KC * ED;
    float4 baseq[4];
#pragma unroll
    for (int ch = 0; ch < 4; ch++) {
        int j = ch * 8 + jb;
        float4 hj4 = *(const float4*)(hjb + (size_t)j * ED + k0);
        baseq[ch] = make_float4(hj4.x + cvq.x, hj4.y + cvq.y,
                                hj4.z + cvq.z, hj4.w + cvq.w);
    }
    float4 b2q = *(const float4*)(fpb2 + n0);
    float4 w3q = *(const float4*)(fpw3 + n0);
    unsigned long long b2p0, b2p1;
    PK2(b2p0, b2q.x, b2q.y);
    PK2(b2p1, b2q.z, b2q.w);
    float b3 = fpb3[0];
    float* pfout = d_pflow + c * 1024;

    for (int i = 0; i < 32; i++) {
        // ---- build h1 row-block for sender i (duplicated float2 for FFMA2) ----
        float4 hi4 = *(const float4*)(hib + (size_t)i * ED + k0);
#pragma unroll
        for (int ch = 0; ch < 4; ch++) {
            int j = ch * 8 + jb;
            float dd = s_dist[i * 32 + j];
            float v0 = fmaxf(fmaf(dd, w1dq.x, baseq[ch].x) + hi4.x, 0.f);
            float v1 = fmaxf(fmaf(dd, w1dq.y, baseq[ch].y) + hi4.y, 0.f);
            float v2 = fmaxf(fmaf(dd, w1dq.z, baseq[ch].z) + hi4.z, 0.f);
            float v3 = fmaxf(fmaf(dd, w1dq.w, baseq[ch].w) + hi4.w, 0.f);
            s_h1f2[j * 128 + k0 + 0] = make_float2(v0, v0);
            s_h1f2[j * 128 + k0 + 1] = make_float2(v1, v1);
            s_h1f2[j * 128 + k0 + 2] = make_float2(v2, v2);
            s_h1f2[j * 128 + k0 + 3] = make_float2(v3, v3);
        }
        __syncthreads();

        // ---- packed-f32x2 GEMM: 2 j x 4 n per thread over K=128 ----
        unsigned long long a00 = b2p0, a01 = b2p1, a10 = b2p0, a11 = b2p1;
        const unsigned long long* h0p = s_h1u + j0 * 128;
        const unsigned long long* h1p = s_h1u + j1 * 128;
#pragma unroll 8
        for (int k = 0; k < 128; k++) {
            unsigned long long h0 = h0p[k];
            unsigned long long h1v = h1p[k];
            ulonglong2 wv = s_w2u2[k * 17 + tx];
            a00 = fma2(h0, wv.x, a00);
            a01 = fma2(h0, wv.y, a01);
            a10 = fma2(h1v, wv.x, a10);
            a11 = fma2(h1v, wv.y, a11);
        }

        // ---- epilogue: relu, dot w3, reduce over 16 n-lanes, softplus ----
        float x0, x1, x2, x3, y0, y1, y2, y3;
        UNPK2(x0, x1, a00); UNPK2(x2, x3, a01);
        UNPK2(y0, y1, a10); UNPK2(y2, y3, a11);
        float v0 = fmaxf(x0, 0.f) * w3q.x + fmaxf(x1, 0.f) * w3q.y
                 + fmaxf(x2, 0.f) * w3q.z + fmaxf(x3, 0.f) * w3q.w;
        float v1 = fmaxf(y0, 0.f) * w3q.x + fmaxf(y1, 0.f) * w3q.y
                 + fmaxf(y2, 0.f) * w3q.z + fmaxf(y3, 0.f) * w3q.w;
#pragma unroll
        for (int o = 8; o > 0; o >>= 1) {
            v0 += __shfl_xor_sync(0xffffffffu, v0, o);
            v1 += __shfl_xor_sync(0xffffffffu, v1, o);
        }
        if (tx == 0) {
            float xx = v0 + b3;
            pfout[i * 32 + j0] = (xx > 20.f) ? xx : log1pf(expf(xx));
            xx = v1 + b3;
            pfout[i * 32 + j1] = (xx > 20.f) ? xx : log1pf(expf(xx));
        }
        __syncthreads();
    }
}

// ---------------- 6. greedy allocation + scatter (warp per cluster) ----------
__global__ void greedy_kernel(float* __restrict__ out) {
    __shared__ float s_effo[KC][KC];
    __shared__ float s_pfo[KC][KC];
    __shared__ float s_flow[KC][KC];
    __shared__ int   s_act[KC][KC];
    __shared__ float s_prio[KC];
    __shared__ float s_neto[KC];
    __shared__ int   s_order[KC];
    __shared__ float s_dnet[KC];
    int c = blockIdx.x, lane = threadIdx.x;

    s_prio[lane] = d_prioc[c * KC + lane];
    __syncwarp();
    float p = s_prio[lane];
    int r = 0;
#pragma unroll
    for (int l = 0; l < KC; l++) {
        float q = s_prio[l];
        r += (q > p) || (q == p && l < lane);
    }
    s_order[r] = lane;
    __syncwarp();
    int oi = s_order[lane];
    s_neto[lane] = d_netc[c * KC + oi];
    const float* effb = d_effc + c * KC * KC;
    const float* pfb  = d_pflow + c * KC * KC;
#pragma unroll 4
    for (int sj = 0; sj < KC; sj++) {
        int oj = s_order[sj];
        s_effo[lane][sj] = effb[oi * KC + oj];
        s_pfo[lane][sj]  = pfb[oi * KC + oj];
        s_flow[lane][sj] = 0.f;
        s_act[lane][sj]  = 0;
    }
    __syncwarp();

    if (lane == 0) {
        float dn[KC];
#pragma unroll
        for (int j = 0; j < KC; j++) dn[j] = s_neto[j];
        for (int i = 0; i < KC; i++) {
            float avail = s_neto[i];
            if (avail > 0.f) {
#pragma unroll 4
                for (int j = 0; j < KC; j++) {
                    float needed = -dn[j];
                    if (needed > 0.f) {
                        float f = fminf(fminf(avail, needed), s_pfo[i][j]);
                        dn[j] += f * s_effo[i][j];
                        avail -= f;
                        s_flow[i][j] = f;
                        s_act[i][j] = 1;
                        if (avail <= 0.f) break;
                    }
                }
            }
        }
#pragma unroll
        for (int j = 0; j < KC; j++) s_dnet[j] = dn[j];
    }
    __syncwarp();

    float* out_sh = out;
    float* out_ef = out + MATSZ;
    float* out_sent = out + 2 * MATSZ + 1;
    float* out_recv = out_sent + NB;
    float* out_na   = out_recv + NB;

    int gi = g_idx[c * KC + oi];
    float sent = 0.f;
#pragma unroll 4
    for (int sj = 0; sj < KC; sj++) {
        float f = s_flow[lane][sj];
        sent += f;
        if (s_act[lane][sj]) {
            int gj = g_idx[c * KC + s_order[sj]];
            out_sh[(size_t)gi * NB + gj] = f;
            out_ef[(size_t)gi * NB + gj] = s_effo[lane][sj];
        }
    }
    out_sent[gi] = sent;
    float dnl = s_dnet[lane];
    out_recv[gi] = dnl - s_neto[lane];
    out_na[gi]   = dnl;

    float v = sent;
#pragma unroll
    for (int o = 16; o > 0; o >>= 1) v += __shfl_down_sync(0xffffffffu, v, o);
    if (lane == 0) d_partial[c] = v;
}

// ---------------- 7. deterministic total reduction ----------------------------
__global__ void total_kernel(float* __restrict__ out) {
    __shared__ float s[NC];
    int t = threadIdx.x;
    s[t] = d_partial[t];
    __syncthreads();
    for (int o = 64; o > 0; o >>= 1) {
        if (t < o) s[t] += s[t + o];
        __syncthreads();
    }
    if (t == 0) out[2 * MATSZ] = s[0];
}

// ------------------------------------------------------------------------------
extern "C" void kernel_launch(void* const* d_in, const int* in_sizes, int n_in,
                              void* d_out, int out_size) {
    const float* emb   = (const float*)d_in[0];
    const float* gen   = (const float*)d_in[1];
    const float* cons  = (const float*)d_in[2];
    const float* pos   = (const float*)d_in[3];
    const float* fpw1  = (const float*)d_in[4];
    const float* fpb1  = (const float*)d_in[5];
    const float* fpw2  = (const float*)d_in[6];
    const float* fpb2  = (const float*)d_in[7];
    const float* fpw3  = (const float*)d_in[8];
    const float* fpb3  = (const float*)d_in[9];
    const float* enw1  = (const float*)d_in[10];
    const float* enb1  = (const float*)d_in[11];
    const float* enw2  = (const float*)d_in[12];
    const float* enb2  = (const float*)d_in[13];
    const float* psw1  = (const float*)d_in[14];
    const float* psb1  = (const float*)d_in[15];
    const float* psw2  = (const float*)d_in[16];
    const float* psb2  = (const float*)d_in[17];
    const int*   assign = (const int*)d_in[18];
    const int*   hour   = (n_in >= 21) ? (const int*)d_in[20] : nullptr;
    float* out = (float*)d_out;

    cudaFuncSetAttribute(pflow_kernel,
                         cudaFuncAttributeMaxDynamicSharedMemorySize, PF_SMEM);

    group_kernel<<<16, 256>>>(assign, gen, cons, hour);
    hij_kernel<<<NC, 256>>>(emb, fpw1);
    prio_kernel<<<512, 256>>>(emb, psw1, psb1, psw2, psb2);
    dist_eff_kernel<<<NC, 256>>>(pos, enw1, enb1, enw2, enb2);
    pflow_kernel<<<NC, 256, PF_SMEM>>>(fpw1, fpb1, fpw2, fpb2, fpw3, fpb3, hour, out);
    greedy_kernel<<<NC, KC>>>(out);
    total_kernel<<<1, NC>>>(out);
}

// round 3
// speedup vs baseline: 2.3065x; 1.6950x over previous
#include <cuda_runtime.h>
#include <math.h>

#define NB 4096
#define NC 128
#define KC 32
#define ED 128
#define MATSZ 16777216ULL   // 4096*4096

__device__ float d_partial[NC];

typedef unsigned long long u64;

__device__ __forceinline__ u64 fma2(u64 a, u64 b, u64 c) {
    u64 d;
    asm("fma.rn.f32x2 %0, %1, %2, %3;" : "=l"(d) : "l"(a), "l"(b), "l"(c));
    return d;
}
#define UNPK2(lo, hi, v) asm("mov.b64 {%0, %1}, %2;" : "=f"(lo), "=f"(hi) : "l"(v))

// ---- dynamic smem word offsets -------------------------------------------
#define W_W2    0        // w2 transposed [k][n] stride 68 floats (also w1-chunk / psw1T staging)
#define W_H1    8704     // h1 duplicated float2 [j][k]  (also emb dup in prologue) 8192 w
#define W_HI    16896    // hi [r][k] 4096 w
#define W_HJ    20992    // hj [r][k] 4096 w
#define W_DIST  25088    // 1024 w
#define W_EFF   26112    // 1024 w
#define W_PF    27136    // 1024 w
#define W_FLOW  28160    // 1024 w (sorted coords)
#define W_GIDX  29184    // int[32]
#define W_NET   29216
#define W_PRIO  29248
#define W_ORD   29280    // int[32]
#define W_ACTB  29312    // unsigned[32]
#define W_DNET  29344
#define W_NSRT  29376
#define W_RSENT 29408
#define W_WCNT  29440    // int[8]
#define W_POS   29448    // float2[32] = 64 words (8B aligned)
#define SM_WORDS 29520
#define SM_BYTES (SM_WORDS * 4)

__global__ void __launch_bounds__(256, 1) mega_kernel(
    const float* __restrict__ emb,  const float* __restrict__ gen,
    const float* __restrict__ cons, const float* __restrict__ pos,
    const float* __restrict__ fpw1, const float* __restrict__ fpb1,
    const float* __restrict__ fpw2, const float* __restrict__ fpb2,
    const float* __restrict__ fpw3, const float* __restrict__ fpb3,
    const float* __restrict__ enw1, const float* __restrict__ enb1,
    const float* __restrict__ enw2, const float* __restrict__ enb2,
    const float* __restrict__ psw1, const float* __restrict__ psb1,
    const float* __restrict__ psw2, const float* __restrict__ psb2,
    const int* __restrict__ assign, const int* __restrict__ hour_p,
    float* __restrict__ out) {
    extern __shared__ float smf[];
    int* s_gidx = (int*)(smf + W_GIDX);
    int* s_ord  = (int*)(smf + W_ORD);
    unsigned* s_actb = (unsigned*)(smf + W_ACTB);
    int* s_wcnt = (int*)(smf + W_WCNT);
    float2* s_pos2 = (float2*)(smf + W_POS);

    const int c = blockIdx.x;
    const int t = threadIdx.x;
    const int w = t >> 5, lane = t & 31;
    const int hour = hour_p ? *hour_p : 12;

    // ================= A. stable grouping (2-pass ballot) ==================
    {
        int a[16];
        const int* ap = assign + w * 512;
#pragma unroll
        for (int q = 0; q < 16; q++) a[q] = ap[q * 32 + lane];
        unsigned balls[16];
        int cnt = 0;
#pragma unroll
        for (int q = 0; q < 16; q++) {
            balls[q] = __ballot_sync(0xffffffffu, a[q] == c);
            cnt += __popc(balls[q]);
        }
        if (lane == 0) s_wcnt[w] = cnt;
        __syncthreads();
        int run = 0;
        for (int ww = 0; ww < 8; ww++) if (ww < w) run += s_wcnt[ww];
#pragma unroll
        for (int q = 0; q < 16; q++) {
            if (a[q] == c) {
                int p = run + __popc(balls[q] & ((1u << lane) - 1u));
                if (p < KC) s_gidx[p] = w * 512 + q * 32 + lane;
            }
            run += __popc(balls[q]);
        }
    }
    __syncthreads();

    // ================= B. net + positions ==================================
    if (t < KC) {
        int b = s_gidx[t];
        smf[W_NET + t] = gen[b * 24 + hour] - cons[b * 24 + hour];
        s_pos2[t] = make_float2(pos[b * 2], pos[b * 2 + 1]);
    }

    // ================= C. stage emb duplicated (float2(v,v)) ==============
    {
        float2* h1f2 = (float2*)(smf + W_H1);
        for (int i = t; i < KC * ED; i += 256) {
            int r = i >> 7, e = i & 127;
            float v = emb[(size_t)s_gidx[r] * ED + e];
            h1f2[r * 128 + e] = make_float2(v, v);
        }
    }

    // ================= D. hij GEMM (FFMA2, packed output col pairs) ========
    {
        float* s_w1c = smf + W_W2;     // [kk][col] stride 258
        const u64* embU = (const u64*)(smf + W_H1);
        int p = t & 127, rh = t >> 7;
        u64 acc[16];
#pragma unroll
        for (int r = 0; r < 16; r++) acc[r] = 0ull;
        for (int kc = 0; kc < 4; kc++) {
            __syncthreads();
            for (int i = t; i < 8192; i += 256) {
                int col = i >> 5, kk = i & 31;
                float v = (col < 128)
                    ? fpw1[(size_t)col * 258 + kc * 32 + kk]
                    : fpw1[(size_t)(col - 128) * 258 + 128 + kc * 32 + kk];
                s_w1c[kk * 258 + col] = v;
            }
            __syncthreads();
            for (int kk = 0; kk < 32; kk++) {
                u64 wp = *(const u64*)(s_w1c + kk * 258 + 2 * p);
                const u64* eb = embU + (rh * 16) * 128 + kc * 32 + kk;
#pragma unroll
                for (int r = 0; r < 16; r++)
                    acc[r] = fma2(eb[r * 128], wp, acc[r]);
            }
        }
        float* dst = (p < 64) ? (smf + W_HI) : (smf + W_HJ);
        int cc = (p < 64) ? 2 * p : 2 * p - 128;
#pragma unroll
        for (int r = 0; r < 16; r++) {
            float lo, hi;
            UNPK2(lo, hi, acc[r]);
            *(float2*)(dst + (rh * 16 + r) * 128 + cc) = make_float2(lo, hi);
        }
    }
    __syncthreads();

    // ================= E. priority MLP =====================================
    {
        float* s_pT = smf + W_W2;      // psw1 transposed [e*33+m]
        for (int i = t; i < 4096; i += 256) {
            int m = i >> 7, e = i & 127;
            s_pT[e * 33 + m] = psw1[i];
        }
        __syncthreads();
        int m = lane, rb = w;
        const float* embF = smf + W_H1;   // duplicated: scalar at idx*2
        float b1m = psb1[m], w2m = psw2[m], b2s = psb2[0];
#pragma unroll
        for (int rr = 0; rr < 4; rr++) {
            int r = rb * 4 + rr;
            float acc = b1m;
#pragma unroll 8
            for (int e = 0; e < 128; e++)
                acc = fmaf(embF[(r * 128 + e) * 2], s_pT[e * 33 + m], acc);
            float v = fmaxf(acc, 0.f) * w2m;
#pragma unroll
            for (int o = 16; o > 0; o >>= 1) v += __shfl_xor_sync(0xffffffffu, v, o);
            if (m == 0) smf[W_PRIO + r] = 1.f / (1.f + expf(-(v + b2s)));
        }
    }

    // ================= F. dist + efficiency ================================
    {
        float b2v = enb2[0];
        for (int pp = t; pp < 1024; pp += 256) {
            int i = pp >> 5, j = pp & 31;
            float2 pi = s_pos2[i], pj = s_pos2[j];
            float dx = pi.x - pj.x, dy = pi.y - pj.y;
            float dist = sqrtf(dx * dx + dy * dy);
            float tq = dist * (1.f / 1000.f);
            float s = 0.f;
#pragma unroll
            for (int l = 0; l < 16; l++)
                s = fmaf(fmaxf(fmaf(tq, __ldg(enw1 + l), __ldg(enb1 + l)), 0.f),
                         __ldg(enw2 + l), s);
            smf[W_EFF + pp] = 0.85f + 0.13f / (1.f + expf(-(s + b2v)));
            smf[W_DIST + pp] = dist;
        }
    }
    __syncthreads();

    // ================= G. stage w2 transposed + per-thread constants =======
    for (int i = t; i < 8192; i += 256) {
        int k = i & 127, n = i >> 7;
        smf[W_W2 + k * 68 + n] = fpw2[n * 128 + k];
    }
    // producer constants: kq strided-k, jb j-base
    const int kq = t & 31, jb = t >> 5;
    float hour_f = (float)hour * (1.f / 24.f);
    float w1dq[4], baseq[4][4];
#pragma unroll
    for (int q = 0; q < 4; q++) {
        int k = kq + 32 * q;
        w1dq[q] = fpw1[(size_t)k * 258 + 256];
        float cv = fmaf(hour_f, fpw1[(size_t)k * 258 + 257], fpb1[k]);
#pragma unroll
        for (int ch = 0; ch < 4; ch++)
            baseq[ch][q] = smf[W_HJ + (ch * 8 + jb) * 128 + k] + cv;
    }
    // consumer constants (threads 0..127): tx = n-quad, jg = j-quad
    const int tx = t & 15, jg = (t >> 4) & 7;
    u64 b2p0 = 0, b2p1 = 0;
    float4 w3q = make_float4(0.f, 0.f, 0.f, 0.f);
    float b3 = fpb3[0];
    if (t < 128) {
        float4 b2q = *(const float4*)(fpb2 + tx * 4);
        w3q = *(const float4*)(fpw3 + tx * 4);
        asm("mov.b64 %0, {%1, %2};" : "=l"(b2p0) : "f"(b2q.x), "f"(b2q.y));
        asm("mov.b64 %0, {%1, %2};" : "=l"(b2p1) : "f"(b2q.z), "f"(b2q.w));
    }
    __syncthreads();

    // ================= H. mainloop over senders i ==========================
    {
        float2* h1f2 = (float2*)(smf + W_H1);
        const u64* h1U = (const u64*)(smf + W_H1);
        const ulonglong2* w2U2 = (const ulonglong2*)(smf + W_W2);
        const float4 z4 = make_float4(0.f, 0.f, 0.f, 0.f);
        const float4 o4 = make_float4(1.f, 1.f, 1.f, 1.f);
        float4* outS4 = (float4*)out;
        float4* outE4 = (float4*)(out + MATSZ);

        for (int i = 0; i < 32; i++) {
            // ---- producer: all 256 threads build h1 (dup) -----------------
            float hiq[4];
#pragma unroll
            for (int q = 0; q < 4; q++) hiq[q] = smf[W_HI + i * 128 + kq + 32 * q];
#pragma unroll
            for (int ch = 0; ch < 4; ch++) {
                int j = ch * 8 + jb;
                float dd = smf[W_DIST + i * 32 + j];
#pragma unroll
                for (int q = 0; q < 4; q++) {
                    float h = fmaxf(fmaf(dd, w1dq[q], baseq[ch][q]) + hiq[q], 0.f);
                    h1f2[j * 128 + kq + 32 * q] = make_float2(h, h);
                }
            }
            __syncthreads();

            if (t < 128) {
                // ---- consumer: 4 j x 4 n per thread over K=128 ------------
                u64 a0x = b2p0, a0y = b2p1, a1x = b2p0, a1y = b2p1;
                u64 a2x = b2p0, a2y = b2p1, a3x = b2p0, a3y = b2p1;
                const u64* h0p = h1U + (jg * 4 + 0) * 128;
                const u64* h1p = h1U + (jg * 4 + 1) * 128;
                const u64* h2p = h1U + (jg * 4 + 2) * 128;
                const u64* h3p = h1U + (jg * 4 + 3) * 128;
#pragma unroll 8
                for (int k = 0; k < 128; k++) {
                    ulonglong2 wv = w2U2[k * 17 + tx];
                    u64 h0 = h0p[k], h1 = h1p[k], h2 = h2p[k], h3 = h3p[k];
                    a0x = fma2(h0, wv.x, a0x); a0y = fma2(h0, wv.y, a0y);
                    a1x = fma2(h1, wv.x, a1x); a1y = fma2(h1, wv.y, a1y);
                    a2x = fma2(h2, wv.x, a2x); a2y = fma2(h2, wv.y, a2y);
                    a3x = fma2(h3, wv.x, a3x); a3y = fma2(h3, wv.y, a3y);
                }
                float v[4];
#pragma unroll
                for (int jj = 0; jj < 4; jj++) {
                    u64 ax = (jj == 0) ? a0x : (jj == 1) ? a1x : (jj == 2) ? a2x : a3x;
                    u64 ay = (jj == 0) ? a0y : (jj == 1) ? a1y : (jj == 2) ? a2y : a3y;
                    float x0, x1, x2, x3;
                    UNPK2(x0, x1, ax); UNPK2(x2, x3, ay);
                    v[jj] = fmaxf(x0, 0.f) * w3q.x + fmaxf(x1, 0.f) * w3q.y
                          + fmaxf(x2, 0.f) * w3q.z + fmaxf(x3, 0.f) * w3q.w;
                }
#pragma unroll
                for (int o = 8; o > 0; o >>= 1) {
#pragma unroll
                    for (int jj = 0; jj < 4; jj++)
                        v[jj] += __shfl_xor_sync(0xffffffffu, v[jj], o);
                }
                if (tx == 0) {
#pragma unroll
                    for (int jj = 0; jj < 4; jj++) {
                        float x = v[jj] + b3;
                        smf[W_PF + i * 32 + jg * 4 + jj] =
                            (x > 20.f) ? x : log1pf(expf(x));
                    }
                }
            } else {
                // ---- filler: warps 4-7 stream the default fill ------------
                int ft = t - 128;
#pragma unroll
                for (int vq = 0; vq < 8; vq++) {
                    int flat = i * 1024 + vq * 128 + ft;
                    int row = flat >> 10, c4 = flat & 1023;
                    size_t base = (size_t)s_gidx[row] * 1024 + c4;
                    outS4[base] = z4;
                    outE4[base] = o4;
                }
            }
            __syncthreads();
        }
    }

    // ================= I. greedy (warp 0, prefix-scan water-filling) =======
    if (w == 0) {
        float pr = smf[W_PRIO + lane];
        int r = 0;
#pragma unroll
        for (int l = 0; l < KC; l++) {
            float q = smf[W_PRIO + l];
            r += (q > pr) || (q == pr && l < lane);
        }
        s_ord[r] = lane;
        __syncwarp();
        int oj = s_ord[lane];
        float nets = smf[W_NET + oj];
        float dn = nets;
        for (int i = 0; i < 32; i++) {
            int oi = s_ord[i];
            float A = fmaxf(__shfl_sync(0xffffffffu, nets, i), 0.f);
            float needed = -dn;
            float pf = smf[W_PF + oi * 32 + oj];
            float cap = (needed > 0.f) ? fminf(needed, pf) : 0.f;
            float C = cap;
#pragma unroll
            for (int o = 1; o < 32; o <<= 1) {
                float x = __shfl_up_sync(0xffffffffu, C, o);
                if (lane >= o) C += x;
            }
            float Cprev = C - cap;
            float avail = A - Cprev;
            bool act = (avail > 0.f) && (needed > 0.f);
            float f = act ? fminf(fminf(avail, needed), pf) : 0.f;
            dn += f * smf[W_EFF + oi * 32 + oj];
            smf[W_FLOW + i * 32 + lane] = f;
            unsigned ab = __ballot_sync(0xffffffffu, act);
            if (lane == 0) s_actb[i] = ab;
        }
        smf[W_DNET + lane] = dn;
        smf[W_NSRT + lane] = nets;
    }
    __syncthreads();

    // ================= J. scatter ==========================================
    {
        float* out_sh = out;
        float* out_ef = out + MATSZ;
        float* out_sent = out + 2 * MATSZ + 1;
        float* out_recv = out_sent + NB;
        float* out_na = out_recv + NB;
        int oj = s_ord[lane];
        int gj = s_gidx[oj];
#pragma unroll
        for (int rr = 0; rr < 4; rr++) {
            int srow = w * 4 + rr;
            int oi = s_ord[srow];
            int gi = s_gidx[oi];
            float f = smf[W_FLOW + srow * 32 + lane];
            unsigned ab = s_actb[srow];
            if ((ab >> lane) & 1u) {
                out_sh[(size_t)gi * NB + gj] = f;
                out_ef[(size_t)gi * NB + gj] = smf[W_EFF + oi * 32 + oj];
            }
            float v = f;
#pragma unroll
            for (int o = 16; o > 0; o >>= 1) v += __shfl_xor_sync(0xffffffffu, v, o);
            if (lane == 0) {
                out_sent[gi] = v;
                float dnl = smf[W_DNET + srow];
                out_recv[gi] = dnl - smf[W_NSRT + srow];
                out_na[gi] = dnl;
                smf[W_RSENT + srow] = v;
            }
        }
    }
    __syncthreads();
    if (t == 0) {
        float tot = 0.f;
#pragma unroll
        for (int i = 0; i < 32; i++) tot += smf[W_RSENT + i];
        d_partial[c] = tot;
    }
}

// ---------------- deterministic total reduction -------------------------------
__global__ void total_kernel(float* __restrict__ out) {
    __shared__ float s[NC];
    int t = threadIdx.x;
    s[t] = d_partial[t];
    __syncthreads();
    for (int o = 64; o > 0; o >>= 1) {
        if (t < o) s[t] += s[t + o];
        __syncthreads();
    }
    if (t == 0) out[2 * MATSZ] = s[0];
}

// ------------------------------------------------------------------------------
extern "C" void kernel_launch(void* const* d_in, const int* in_sizes, int n_in,
                              void* d_out, int out_size) {
    const float* emb   = (const float*)d_in[0];
    const float* gen   = (const float*)d_in[1];
    const float* cons  = (const float*)d_in[2];
    const float* pos   = (const float*)d_in[3];
    const float* fpw1  = (const float*)d_in[4];
    const float* fpb1  = (const float*)d_in[5];
    const float* fpw2  = (const float*)d_in[6];
    const float* fpb2  = (const float*)d_in[7];
    const float* fpw3  = (const float*)d_in[8];
    const float* fpb3  = (const float*)d_in[9];
    const float* enw1  = (const float*)d_in[10];
    const float* enb1  = (const float*)d_in[11];
    const float* enw2  = (const float*)d_in[12];
    const float* enb2  = (const float*)d_in[13];
    const float* psw1  = (const float*)d_in[14];
    const float* psb1  = (const float*)d_in[15];
    const float* psw2  = (const float*)d_in[16];
    const float* psb2  = (const float*)d_in[17];
    const int*   assign = (const int*)d_in[18];
    const int*   hour   = (n_in >= 21) ? (const int*)d_in[20] : nullptr;
    float* out = (float*)d_out;

    static int configured = 0;
    if (!configured) {
        cudaFuncSetAttribute(mega_kernel,
                             cudaFuncAttributeMaxDynamicSharedMemorySize, SM_BYTES);
        configured = 1;
    }

    mega_kernel<<<NC, 256, SM_BYTES>>>(emb, gen, cons, pos,
                                       fpw1, fpb1, fpw2, fpb2, fpw3, fpb3,
                                       enw1, enb1, enw2, enb2,
                                       psw1, psb1, psw2, psb2,
                                       assign, hour, out);
    total_kernel<<<1, NC>>>(out);
}